// round 7
// baseline (speedup 1.0000x reference)
#include <cuda_runtime.h>
#include <math.h>

// Problem constants (reference: S=2048, B=32, H=1024)
#define SDIM 2048
#define BDIM 32
#define HDIM 1024
#define KSPLIT 32
#define KCHUNK (HDIM / KSPLIT)   // 32
#define S_PER_WARP 8             // v-register reuse factor in k_energies

// Scratch (allocation-free rule: __device__ globals)
__device__ float g_vpart[KSPLIT * BDIM * HDIM];   // 4 MB
__device__ float g_v[BDIM * HDIM];                // 128 KB
__device__ float g_energies[BDIM * SDIM];         // 256 KB

// ---------------------------------------------------------------------------
// Stage 1: v-partials.  v[b,h] = sum_k dec[b,k] * W[k,h], split over k.
// Grid: (HDIM/128, KSPLIT) x 128 threads = 256 blocks. Each thread owns one
// h, accumulates all 32 b in registers; W read exactly once chip-wide (4 MB).
// Per-thread: KCHUNK*BDIM = 1024 FFMA -> ~2048 cyc -> ~1.1 us.
// ---------------------------------------------------------------------------
__global__ void __launch_bounds__(128)
k_proj_partial(const float* __restrict__ dec,
               const float* __restrict__ W) {
    __shared__ float sdec[BDIM * KCHUNK];   // 4 KB
    const int h  = blockIdx.x * 128 + threadIdx.x;
    const int k0 = blockIdx.y * KCHUNK;

    for (int i = threadIdx.x; i < BDIM * KCHUNK; i += 128) {
        int b  = i / KCHUNK;
        int kk = i % KCHUNK;
        sdec[i] = dec[b * HDIM + k0 + kk];
    }
    __syncthreads();

    float acc[BDIM];
#pragma unroll
    for (int b = 0; b < BDIM; b++) acc[b] = 0.f;

    for (int kk = 0; kk < KCHUNK; kk++) {
        const float w = W[(size_t)(k0 + kk) * HDIM + h];   // coalesced
#pragma unroll
        for (int b = 0; b < BDIM; b++)
            acc[b] = fmaf(sdec[b * KCHUNK + kk], w, acc[b]);   // smem broadcast
    }

#pragma unroll
    for (int b = 0; b < BDIM; b++)
        g_vpart[((size_t)blockIdx.y * BDIM + b) * HDIM + h] = acc[b];
}

// ---------------------------------------------------------------------------
// Stage 2: reduce KSPLIT partials into v.  32768 outputs, 4 MB read.
// ---------------------------------------------------------------------------
__global__ void __launch_bounds__(256)
k_reduce_v() {
    const int i = blockIdx.x * 256 + threadIdx.x;   // < BDIM*HDIM
    float s = 0.f;
#pragma unroll
    for (int p = 0; p < KSPLIT; p++)
        s += g_vpart[(size_t)p * BDIM * HDIM + i];
    g_v[i] = s;
}

// ---------------------------------------------------------------------------
// Stage 3: energies[b,s] = <v[b], enc[s,b,:]>.
// One warp handles ONE b and S_PER_WARP s-values, keeping v[b] resident in
// registers (8 x float4 per lane). v L2 traffic is 32 MB (8x cut vs naive);
// enc is read exactly once (256 MB) -> HBM-bound, ~35-40 us.
// __launch_bounds__(256, 8): 64 warps/SM so in-flight LDG.128 count covers
// the 577-cycle DRAM latency without register spills.
// ---------------------------------------------------------------------------
__global__ void __launch_bounds__(256, 8)
k_energies(const float* __restrict__ enc) {
    const int w    = blockIdx.x * (blockDim.x >> 5) + (threadIdx.x >> 5);
    const int lane = threadIdx.x & 31;
    const int b    = w & (BDIM - 1);          // warp's batch row
    const int sg   = w >> 5;                  // s-group 0..(SDIM/S_PER_WARP)-1
    const int s0   = sg * S_PER_WARP;

    const float4* __restrict__ v4 =
        reinterpret_cast<const float4*>(g_v + (size_t)b * HDIM);
    float4 v[8];
#pragma unroll
    for (int j = 0; j < 8; j++) v[j] = v4[lane + j * 32];

#pragma unroll
    for (int t = 0; t < S_PER_WARP; t++) {
        const int s = s0 + t;
        const float4* __restrict__ e4 =
            reinterpret_cast<const float4*>(enc + ((size_t)s * BDIM + b) * HDIM);

        // 8 independent LDG.128 front-batched for MLP, then FMA chain.
        float4 e[8];
#pragma unroll
        for (int j = 0; j < 8; j++) e[j] = e4[lane + j * 32];

        float acc = 0.f;
#pragma unroll
        for (int j = 0; j < 8; j++) {
            acc = fmaf(e[j].x, v[j].x, acc);
            acc = fmaf(e[j].y, v[j].y, acc);
            acc = fmaf(e[j].z, v[j].z, acc);
            acc = fmaf(e[j].w, v[j].w, acc);
        }
#pragma unroll
        for (int off = 16; off; off >>= 1)
            acc += __shfl_xor_sync(0xffffffffu, acc, off);

        if (lane == 0)
            g_energies[(size_t)b * SDIM + s] = acc;
    }
}

// ---------------------------------------------------------------------------
// Stage 4: row softmax over S per b.  The dec·bias term is a per-b constant
// and cancels under softmax shift-invariance -> never computed.
// ---------------------------------------------------------------------------
__global__ void __launch_bounds__(256)
k_softmax(float* __restrict__ out) {
    const int b   = blockIdx.x;
    const int tid = threadIdx.x;
    const float* __restrict__ e = g_energies + (size_t)b * SDIM;

    float vals[8];
    float m = -INFINITY;
#pragma unroll
    for (int j = 0; j < 8; j++) {
        vals[j] = e[tid + j * 256];
        m = fmaxf(m, vals[j]);
    }

    __shared__ float redm[8];
    __shared__ float reds[8];

#pragma unroll
    for (int off = 16; off; off >>= 1)
        m = fmaxf(m, __shfl_xor_sync(0xffffffffu, m, off));
    if ((tid & 31) == 0) redm[tid >> 5] = m;
    __syncthreads();
    float bm = redm[0];
#pragma unroll
    for (int i = 1; i < 8; i++) bm = fmaxf(bm, redm[i]);

    float ex[8];
    float ssum = 0.f;
#pragma unroll
    for (int j = 0; j < 8; j++) {
        ex[j] = expf(vals[j] - bm);
        ssum += ex[j];
    }
#pragma unroll
    for (int off = 16; off; off >>= 1)
        ssum += __shfl_xor_sync(0xffffffffu, ssum, off);
    if ((tid & 31) == 0) reds[tid >> 5] = ssum;
    __syncthreads();
    float tot = 0.f;
#pragma unroll
    for (int i = 0; i < 8; i++) tot += reds[i];

    const float inv = 1.0f / tot;
#pragma unroll
    for (int j = 0; j < 8; j++)
        out[(size_t)b * SDIM + tid + j * 256] = ex[j] * inv;
}

// ---------------------------------------------------------------------------
extern "C" void kernel_launch(void* const* d_in, const int* in_sizes, int n_in,
                              void* d_out, int out_size) {
    // Bind inputs by element count (order-proof; all four counts distinct):
    //   dec [B,H]   = 32768
    //   enc [S,B,H] = 67108864
    //   W   [H,H]   = 1048576
    //   b   [H]     = 1024  (cancels under softmax -> unused)
    const float* dec = nullptr;
    const float* enc = nullptr;
    const float* W   = nullptr;
    for (int i = 0; i < n_in; i++) {
        switch (in_sizes[i]) {
            case BDIM * HDIM:         dec = (const float*)d_in[i]; break;
            case SDIM * BDIM * HDIM:  enc = (const float*)d_in[i]; break;
            case HDIM * HDIM:         W   = (const float*)d_in[i]; break;
            default: break;           // bias (HDIM) or unknown: ignored
        }
    }
    float* out = (float*)d_out;                 // [B, 1, S]
    (void)out_size;

    k_proj_partial<<<dim3(HDIM / 128, KSPLIT), 128>>>(dec, W);
    k_reduce_v<<<(BDIM * HDIM) / 256, 256>>>();
    // warps total = (SDIM/S_PER_WARP)*BDIM = 8192; 8 warps/block -> 1024 blocks
    k_energies<<<(SDIM / S_PER_WARP) * BDIM / 8, 256>>>(enc);
    k_softmax<<<BDIM, 256>>>(out);
}

// round 14
// speedup vs baseline: 1.1931x; 1.1931x over previous
#include <cuda_runtime.h>
#include <math.h>

// Problem constants (reference: S=2048, B=32, H=1024)
#define SDIM 2048
#define BDIM 32
#define HDIM 1024
#define KSPLIT 32
#define KCHUNK (HDIM / KSPLIT)   // 32
#define S_PER_WARP 8             // s-values per warp in k_energies

// Scratch (allocation-free rule: __device__ globals)
__device__ float g_vpart[KSPLIT * BDIM * HDIM];   // 4 MB
__device__ float g_v[BDIM * HDIM];                // 128 KB
__device__ float g_energies[BDIM * SDIM];         // 256 KB

// ---------------------------------------------------------------------------
// Stage 1: v-partials.  v[b,h] = sum_k dec[b,k] * W[k,h], split over k.
// ---------------------------------------------------------------------------
__global__ void __launch_bounds__(128)
k_proj_partial(const float* __restrict__ dec,
               const float* __restrict__ W) {
    __shared__ float sdec[BDIM * KCHUNK];   // 4 KB
    const int h  = blockIdx.x * 128 + threadIdx.x;
    const int k0 = blockIdx.y * KCHUNK;

    for (int i = threadIdx.x; i < BDIM * KCHUNK; i += 128) {
        int b  = i / KCHUNK;
        int kk = i % KCHUNK;
        sdec[i] = dec[b * HDIM + k0 + kk];
    }
    __syncthreads();

    float acc[BDIM];
#pragma unroll
    for (int b = 0; b < BDIM; b++) acc[b] = 0.f;

    for (int kk = 0; kk < KCHUNK; kk++) {
        const float w = W[(size_t)(k0 + kk) * HDIM + h];   // coalesced
#pragma unroll
        for (int b = 0; b < BDIM; b++)
            acc[b] = fmaf(sdec[b * KCHUNK + kk], w, acc[b]);   // smem broadcast
    }

#pragma unroll
    for (int b = 0; b < BDIM; b++)
        g_vpart[((size_t)blockIdx.y * BDIM + b) * HDIM + h] = acc[b];
}

// ---------------------------------------------------------------------------
// Stage 2: reduce KSPLIT partials into v.  32768 outputs, 4 MB read.
// ---------------------------------------------------------------------------
__global__ void __launch_bounds__(256)
k_reduce_v() {
    const int i = blockIdx.x * 256 + threadIdx.x;   // < BDIM*HDIM
    float s = 0.f;
#pragma unroll
    for (int p = 0; p < KSPLIT; p++)
        s += g_vpart[(size_t)p * BDIM * HDIM + i];
    g_v[i] = s;
}

// ---------------------------------------------------------------------------
// Stage 3: energies[b,s] = <v[b], enc[s,b,:]>.
// One BLOCK owns one b; all 8 warps share v[b] in 4 KB smem (filled once).
// Each warp does S_PER_WARP s-values with 8 front-batched LDG.128 (MLP=8).
// Register budget: e[8] (32) + temps ~ 50 regs -> fits the 64-reg budget of
// __launch_bounds__(256,4) with NO spills (Round-7 bug: (256,8) capped regs
// at 32 and silently spilled v[]/e[] to local memory).
// 4 blocks x 8 warps = 32 warps/SM; 32 KB in-flight > 17 KB needed for DRAM.
// ---------------------------------------------------------------------------
__global__ void __launch_bounds__(256, 4)
k_energies(const float* __restrict__ enc) {
    __shared__ float4 sv[HDIM / 4];          // v[b], 4 KB
    const int tid  = threadIdx.x;
    const int lane = tid & 31;
    const int widx = tid >> 5;               // 0..7
    const int b    = blockIdx.x & (BDIM - 1);
    const int sg   = (blockIdx.x >> 5) * 8 + widx;   // 0..255
    const int s0   = sg * S_PER_WARP;

    // Fill v[b] into smem: 256 threads x 1 float4 = 4 KB.
    sv[tid] = reinterpret_cast<const float4*>(g_v + (size_t)b * HDIM)[tid];
    __syncthreads();

#pragma unroll
    for (int t = 0; t < S_PER_WARP; t++) {
        const int s = s0 + t;
        const float4* __restrict__ e4 =
            reinterpret_cast<const float4*>(enc + ((size_t)s * BDIM + b) * HDIM);

        // 8 independent LDG.128 front-batched for MLP.
        float4 e[8];
#pragma unroll
        for (int j = 0; j < 8; j++) e[j] = e4[lane + j * 32];

        float acc = 0.f;
#pragma unroll
        for (int j = 0; j < 8; j++) {
            const float4 v = sv[lane + j * 32];   // conflict-free LDS.128
            acc = fmaf(e[j].x, v.x, acc);
            acc = fmaf(e[j].y, v.y, acc);
            acc = fmaf(e[j].z, v.z, acc);
            acc = fmaf(e[j].w, v.w, acc);
        }
#pragma unroll
        for (int off = 16; off; off >>= 1)
            acc += __shfl_xor_sync(0xffffffffu, acc, off);

        if (lane == 0)
            g_energies[(size_t)b * SDIM + s] = acc;
    }
}

// ---------------------------------------------------------------------------
// Stage 4: row softmax over S per b.  1024 threads, 2 elems/thread (shorter
// serial chains than 256x8).  Bias term cancels under softmax shift-invariance.
// ---------------------------------------------------------------------------
__global__ void __launch_bounds__(1024)
k_softmax(float* __restrict__ out) {
    const int b    = blockIdx.x;
    const int tid  = threadIdx.x;
    const int lane = tid & 31;
    const int wid  = tid >> 5;
    const float* __restrict__ e = g_energies + (size_t)b * SDIM;

    const float v0 = e[tid];
    const float v1 = e[tid + 1024];

    __shared__ float redm[32];
    __shared__ float reds[32];

    float m = fmaxf(v0, v1);
#pragma unroll
    for (int off = 16; off; off >>= 1)
        m = fmaxf(m, __shfl_xor_sync(0xffffffffu, m, off));
    if (lane == 0) redm[wid] = m;
    __syncthreads();
    float bm = redm[0];
#pragma unroll
    for (int i = 1; i < 32; i++) bm = fmaxf(bm, redm[i]);

    const float e0 = expf(v0 - bm);
    const float e1 = expf(v1 - bm);
    float ssum = e0 + e1;
#pragma unroll
    for (int off = 16; off; off >>= 1)
        ssum += __shfl_xor_sync(0xffffffffu, ssum, off);
    if (lane == 0) reds[wid] = ssum;
    __syncthreads();
    float tot = 0.f;
#pragma unroll
    for (int i = 0; i < 32; i++) tot += reds[i];

    const float inv = 1.0f / tot;
    out[(size_t)b * SDIM + tid]        = e0 * inv;
    out[(size_t)b * SDIM + tid + 1024] = e1 * inv;
}

// ---------------------------------------------------------------------------
extern "C" void kernel_launch(void* const* d_in, const int* in_sizes, int n_in,
                              void* d_out, int out_size) {
    // Bind inputs by element count (order-proof; all four counts distinct):
    //   dec [B,H]=32768, enc [S,B,H]=67108864, W [H,H]=1048576, bias [H]=1024
    const float* dec = nullptr;
    const float* enc = nullptr;
    const float* W   = nullptr;
    for (int i = 0; i < n_in; i++) {
        switch (in_sizes[i]) {
            case BDIM * HDIM:         dec = (const float*)d_in[i]; break;
            case SDIM * BDIM * HDIM:  enc = (const float*)d_in[i]; break;
            case HDIM * HDIM:         W   = (const float*)d_in[i]; break;
            default: break;           // bias: cancels under softmax -> unused
        }
    }
    float* out = (float*)d_out;                 // [B, 1, S]
    (void)out_size;

    k_proj_partial<<<dim3(HDIM / 128, KSPLIT), 128>>>(dec, W);
    k_reduce_v<<<(BDIM * HDIM) / 256, 256>>>();
    k_energies<<<(SDIM / S_PER_WARP) * BDIM / 8, 256>>>(enc);   // 1024 blocks
    k_softmax<<<BDIM, 1024>>>(out);
}